// round 17
// baseline (speedup 1.0000x reference)
#include <cuda_runtime.h>
#include <cuda_bf16.h>
#include <math.h>
#include <stdint.h>

#define NN 100000
#define EE 1600000
#define DIM 128
#define HEADS 4
#define HC 32

// ---------------- device scratch ----------------
__device__ float g_agg[NN * DIM];   // (1+eps)*x + sum relu(x[src]+ea)
__device__ float g_h[NN * DIM];     // LN1(relu(MLP)) + x
__device__ float g_xp[NN * DIM];    // h @ gat_w
__device__ float g_asrc[NN * HEADS];
__device__ float g_adst[NN * HEADS];

// CSR by dst
__device__ int g_deg[NN];
__device__ int g_off[NN + 1];
__device__ int g_cursor[NN];
__device__ int g_bsum[128];
__device__ int g_boff[128];
__device__ int g_src_sorted[EE];
__device__ int g_eid_sorted[EE];

// ---------------- CSR build ----------------
__global__ __launch_bounds__(1024) void k_zero_deg() {
    int g = blockIdx.x * 1024 + threadIdx.x;
    if (g < NN) g_deg[g] = 0;
}

__global__ __launch_bounds__(256) void k_hist(const int* __restrict__ ei) {
    int e = blockIdx.x * 256 + threadIdx.x;   // grid sized exactly EE/256
    atomicAdd(&g_deg[ei[EE + e]], 1);
}

__global__ __launch_bounds__(1024) void k_scan1() {
    __shared__ int s[1024];
    int tid = threadIdx.x;
    int g = blockIdx.x * 1024 + tid;
    int v = (g < NN) ? g_deg[g] : 0;
    s[tid] = v;
    __syncthreads();
    #pragma unroll
    for (int off = 1; off < 1024; off <<= 1) {
        int t = (tid >= off) ? s[tid - off] : 0;
        __syncthreads();
        s[tid] += t;
        __syncthreads();
    }
    if (g < NN) g_off[g] = s[tid] - v;          // exclusive, block-local
    if (tid == 1023) g_bsum[blockIdx.x] = s[1023];
}

__global__ __launch_bounds__(128) void k_scan2(int nb) {
    __shared__ int s[128];
    int tid = threadIdx.x;
    int v = (tid < nb) ? g_bsum[tid] : 0;
    s[tid] = v;
    __syncthreads();
    #pragma unroll
    for (int off = 1; off < 128; off <<= 1) {
        int t = (tid >= off) ? s[tid - off] : 0;
        __syncthreads();
        s[tid] += t;
        __syncthreads();
    }
    if (tid < nb) g_boff[tid] = s[tid] - v;     // exclusive
}

__global__ __launch_bounds__(1024) void k_scan3() {
    int g = blockIdx.x * 1024 + threadIdx.x;
    if (g < NN) {
        int o = g_off[g] + g_boff[blockIdx.x];
        g_off[g] = o;
        g_cursor[g] = o;
    }
    if (g == 0) g_off[NN] = EE;
}

__global__ __launch_bounds__(256) void k_scatter(const int* __restrict__ ei) {
    int e = blockIdx.x * 256 + threadIdx.x;
    int d = ei[EE + e];
    int pos = atomicAdd(&g_cursor[d], 1);
    g_src_sorted[pos] = ei[e];
    g_eid_sorted[pos] = e;
}

// ---------------- GINE gather: warp per node, no atomics ----------------
__global__ __launch_bounds__(256) void k_gine_gather(const float* __restrict__ x,
                                                     const float* __restrict__ ea,
                                                     const float* __restrict__ eps) {
    int node = (blockIdx.x * 256 + threadIdx.x) >> 5;
    int lane = threadIdx.x & 31;
    if (node >= NN) return;
    const float4* x4 = (const float4*)x;
    const float4* ea4 = (const float4*)ea;

    float e1 = 1.0f + eps[0];
    float4 acc = x4[(size_t)node * 32 + lane];
    acc.x *= e1; acc.y *= e1; acc.z *= e1; acc.w *= e1;

    int o0 = g_off[node], o1 = g_off[node + 1];
    for (int base = o0; base < o1; base += 32) {
        int rem = o1 - base;
        int m = rem < 32 ? rem : 32;
        int sj = 0, ej = 0;
        if (lane < m) { sj = g_src_sorted[base + lane]; ej = g_eid_sorted[base + lane]; }
        for (int j = 0; j < m; j++) {
            int s = __shfl_sync(0xffffffffu, sj, j);
            int e = __shfl_sync(0xffffffffu, ej, j);
            float4 xs = __ldg(&x4[(size_t)s * 32 + lane]);
            float4 ev = __ldg(&ea4[(size_t)e * 32 + lane]);
            acc.x += fmaxf(xs.x + ev.x, 0.f);
            acc.y += fmaxf(xs.y + ev.y, 0.f);
            acc.z += fmaxf(xs.z + ev.z, 0.f);
            acc.w += fmaxf(xs.w + ev.w, 0.f);
        }
    }
    ((float4*)g_agg)[(size_t)node * 32 + lane] = acc;
}

// ---------------- tf32-split tensor-core GEMM machinery -------------------
#define A_LD 132      // A_s row stride (floats): banks (4*qr + qc) -> conflict-free A frags
#define W_LD 136      // W_s row stride (floats): banks (8*qc + qr) -> conflict-free B frags
#define A_FL (64 * A_LD)
#define W_FL (128 * W_LD)
#define SMEM_BYTES ((A_FL + W_FL) * 4)

__device__ __forceinline__ void split_tf32(float x, uint32_t& hi, uint32_t& lo) {
    asm("cvt.rna.tf32.f32 %0, %1;" : "=r"(hi) : "f"(x));
    float r = x - __uint_as_float(hi);
    asm("cvt.rna.tf32.f32 %0, %1;" : "=r"(lo) : "f"(r));
}

__device__ __forceinline__ void mma_tf32(float c[4], const uint32_t a[4], const uint32_t b[2]) {
    asm volatile("mma.sync.aligned.m16n8k8.row.col.f32.tf32.tf32.f32 "
                 "{%0,%1,%2,%3},{%4,%5,%6,%7},{%8,%9},{%0,%1,%2,%3};"
                 : "+f"(c[0]), "+f"(c[1]), "+f"(c[2]), "+f"(c[3])
                 : "r"(a[0]), "r"(a[1]), "r"(a[2]), "r"(a[3]), "r"(b[0]), "r"(b[1]));
}

// one 64x128x128 GEMM pass: acc += A_s @ W_s (fp32-accurate via tf32 split)
__device__ __forceinline__ void mma_stage(float c[2][4][4], const float* A_s, const float* W_s,
                                          int wm, int wn, int qr, int qc) {
    #pragma unroll 2
    for (int k0 = 0; k0 < DIM; k0 += 8) {
        uint32_t ah[2][4], al[2][4];
        #pragma unroll
        for (int i = 0; i < 2; i++) {
            int rb = wm * 32 + i * 16 + qr;
            float a0 = A_s[rb * A_LD + k0 + qc];
            float a1 = A_s[(rb + 8) * A_LD + k0 + qc];
            float a2 = A_s[rb * A_LD + k0 + 4 + qc];
            float a3 = A_s[(rb + 8) * A_LD + k0 + 4 + qc];
            split_tf32(a0, ah[i][0], al[i][0]);
            split_tf32(a1, ah[i][1], al[i][1]);
            split_tf32(a2, ah[i][2], al[i][2]);
            split_tf32(a3, ah[i][3], al[i][3]);
        }
        uint32_t bh[4][2], bl[4][2];
        #pragma unroll
        for (int j = 0; j < 4; j++) {
            int nc = wn * 32 + j * 8 + qr;
            float b0 = W_s[(k0 + qc) * W_LD + nc];
            float b1 = W_s[(k0 + 4 + qc) * W_LD + nc];
            split_tf32(b0, bh[j][0], bl[j][0]);
            split_tf32(b1, bh[j][1], bl[j][1]);
        }
        #pragma unroll
        for (int i = 0; i < 2; i++)
            #pragma unroll
            for (int j = 0; j < 4; j++) {
                mma_tf32(c[i][j], ah[i], bh[j]);   // hi*hi
                mma_tf32(c[i][j], ah[i], bl[j]);   // hi*lo
                mma_tf32(c[i][j], al[i], bh[j]);   // lo*hi
            }
    }
}

__device__ __forceinline__ void acc_init_bias(float c[2][4][4], const float* bias, int wn, int qc) {
    #pragma unroll
    for (int j = 0; j < 4; j++) {
        int col = wn * 32 + j * 8 + 2 * qc;
        float b0 = bias ? __ldg(bias + col) : 0.f;
        float b1 = bias ? __ldg(bias + col + 1) : 0.f;
        #pragma unroll
        for (int i = 0; i < 2; i++) {
            c[i][j][0] = b0; c[i][j][1] = b1; c[i][j][2] = b0; c[i][j][3] = b1;
        }
    }
}

template <bool RELU>
__device__ __forceinline__ void acc_store(const float c[2][4][4], float* A_s,
                                          int wm, int wn, int qr, int qc) {
    #pragma unroll
    for (int i = 0; i < 2; i++) {
        int row = wm * 32 + i * 16 + qr;
        #pragma unroll
        for (int j = 0; j < 4; j++) {
            int col = wn * 32 + j * 8 + 2 * qc;
            float v0 = c[i][j][0], v1 = c[i][j][1], v2 = c[i][j][2], v3 = c[i][j][3];
            if (RELU) { v0 = fmaxf(v0, 0.f); v1 = fmaxf(v1, 0.f);
                        v2 = fmaxf(v2, 0.f); v3 = fmaxf(v3, 0.f); }
            *(float2*)(A_s + row * A_LD + col)       = make_float2(v0, v1);
            *(float2*)(A_s + (row + 8) * A_LD + col) = make_float2(v2, v3);
        }
    }
}

// ---------------- fused 3-stage tensor-core GEMM (MLP + LN1 + gat proj) ----
__global__ __launch_bounds__(256, 2) void k_fused_gemm(
    const float* __restrict__ x,
    const float* __restrict__ w1, const float* __restrict__ b1,
    const float* __restrict__ w2, const float* __restrict__ b2,
    const float* __restrict__ ln1g, const float* __restrict__ ln1b,
    const float* __restrict__ gatw,
    const float* __restrict__ atts, const float* __restrict__ attd) {
    extern __shared__ float smem[];
    float* W_s = smem;            // 128 x W_LD
    float* A_s = smem + W_FL;     // 64 x A_LD

    const int t = threadIdx.x;
    const int lane = t & 31;
    const int wid = t >> 5;           // 0..7
    const int wm = wid & 1;           // 2 warps along M (32 rows each)
    const int wn = wid >> 1;          // 4 warps along N (32 cols each)
    const int qr = lane >> 2;
    const int qc = lane & 3;
    const int row0 = blockIdx.x * 64;

    // ---- stage W1 (padded) + A tile from g_agg (padded) ----
    #pragma unroll
    for (int i = 0; i < 16; i++) {
        int idx = t + 256 * i;                 // 4096 float4
        ((float4*)W_s)[(idx >> 5) * (W_LD / 4) + (idx & 31)] = ((const float4*)w1)[idx];
    }
    #pragma unroll
    for (int i = 0; i < 8; i++) {
        int idx = t + 256 * i;                 // 2048 float4
        int r = idx >> 5;
        float4 v = (row0 + r < NN) ? ((const float4*)g_agg)[(size_t)(row0 + r) * 32 + (idx & 31)]
                                   : make_float4(0.f, 0.f, 0.f, 0.f);
        ((float4*)A_s)[r * (A_LD / 4) + (idx & 31)] = v;
    }
    __syncthreads();

    float acc[2][4][4];

    // ---- GEMM1: relu(agg@W1 + b1) -> A_s ----
    acc_init_bias(acc, b1, wn, qc);
    mma_stage(acc, A_s, W_s, wm, wn, qr, qc);
    __syncthreads();
    acc_store<true>(acc, A_s, wm, wn, qr, qc);
    #pragma unroll
    for (int i = 0; i < 16; i++) {
        int idx = t + 256 * i;
        ((float4*)W_s)[(idx >> 5) * (W_LD / 4) + (idx & 31)] = ((const float4*)w2)[idx];
    }
    __syncthreads();

    // ---- GEMM2: .@W2 + b2 ----
    acc_init_bias(acc, b2, wn, qc);
    mma_stage(acc, A_s, W_s, wm, wn, qr, qc);
    __syncthreads();
    acc_store<false>(acc, A_s, wm, wn, qr, qc);
    __syncthreads();

    // ---- LN1 row pass: relu -> LN -> +x, write g_h and A_s; also stage gat_w
    {
        float4 g4 = ((const float4*)ln1g)[lane];
        float4 bb = ((const float4*)ln1b)[lane];
        #pragma unroll
        for (int rr = 0; rr < 8; rr++) {
            int r = wid * 8 + rr;
            int row = row0 + r;
            float4 v = ((float4*)(A_s + r * A_LD))[lane];
            v.x = fmaxf(v.x, 0.f); v.y = fmaxf(v.y, 0.f);
            v.z = fmaxf(v.z, 0.f); v.w = fmaxf(v.w, 0.f);
            float s = v.x + v.y + v.z + v.w;
            #pragma unroll
            for (int o = 16; o; o >>= 1) s += __shfl_xor_sync(0xffffffffu, s, o);
            float mu = s * (1.0f / DIM);
            float dx = v.x - mu, dy = v.y - mu, dz = v.z - mu, dw = v.w - mu;
            float ss = dx * dx + dy * dy + dz * dz + dw * dw;
            #pragma unroll
            for (int o = 16; o; o >>= 1) ss += __shfl_xor_sync(0xffffffffu, ss, o);
            float inv = rsqrtf(ss * (1.0f / DIM) + 1e-5f);
            float4 res = (row < NN) ? ((const float4*)x)[(size_t)row * 32 + lane]
                                    : make_float4(0.f, 0.f, 0.f, 0.f);
            float4 o4;
            o4.x = dx * inv * g4.x + bb.x + res.x;
            o4.y = dy * inv * g4.y + bb.y + res.y;
            o4.z = dz * inv * g4.z + bb.z + res.z;
            o4.w = dw * inv * g4.w + bb.w + res.w;
            if (row < NN) ((float4*)g_h)[(size_t)row * 32 + lane] = o4;
            ((float4*)(A_s + r * A_LD))[lane] = o4;
        }
        #pragma unroll
        for (int i = 0; i < 16; i++) {
            int idx = t + 256 * i;
            ((float4*)W_s)[(idx >> 5) * (W_LD / 4) + (idx & 31)] = ((const float4*)gatw)[idx];
        }
    }
    __syncthreads();

    // ---- GEMM3: h@gat_w -> xp + attention coefficients ----
    acc_init_bias(acc, nullptr, wn, qc);
    mma_stage(acc, A_s, W_s, wm, wn, qr, qc);
    __syncthreads();
    acc_store<false>(acc, A_s, wm, wn, qr, qc);
    __syncthreads();

    {
        float4 as = ((const float4*)atts)[lane];
        float4 ad = ((const float4*)attd)[lane];
        #pragma unroll
        for (int rr = 0; rr < 8; rr++) {
            int r = wid * 8 + rr;
            int row = row0 + r;
            float4 v = ((float4*)(A_s + r * A_LD))[lane];
            float ps = v.x * as.x + v.y * as.y + v.z * as.z + v.w * as.w;
            float pd = v.x * ad.x + v.y * ad.y + v.z * ad.z + v.w * ad.w;
            #pragma unroll
            for (int o = 4; o; o >>= 1) {
                ps += __shfl_down_sync(0xffffffffu, ps, o, 8);
                pd += __shfl_down_sync(0xffffffffu, pd, o, 8);
            }
            if (row < NN) {
                ((float4*)g_xp)[(size_t)row * 32 + lane] = v;
                if ((lane & 7) == 0) {
                    g_asrc[row * HEADS + (lane >> 3)] = ps;
                    g_adst[row * HEADS + (lane >> 3)] = pd;
                }
            }
        }
    }
}

// ---------------- GAT gather: warp per node, fused softmax+norm+LN2+resid --
__global__ __launch_bounds__(256) void k_gat_gather(const float* __restrict__ gat_b,
                                                    const float* __restrict__ ln2g,
                                                    const float* __restrict__ ln2b,
                                                    float* __restrict__ outp) {
    int node = (blockIdx.x * 256 + threadIdx.x) >> 5;
    int lane = threadIdx.x & 31;
    if (node >= NN) return;
    const float4* xp4 = (const float4*)g_xp;
    int h = lane >> 3;

    float adst_d = g_adst[node * HEADS + h];
    // self loop
    float l = g_asrc[node * HEADS + h] + adst_d;
    l = (l > 0.f) ? l : 0.2f * l;
    float w = __expf(l);
    float wsum = w;
    float4 xv = xp4[(size_t)node * 32 + lane];
    float4 acc = make_float4(w * xv.x, w * xv.y, w * xv.z, w * xv.w);

    int o0 = g_off[node], o1 = g_off[node + 1];
    for (int base = o0; base < o1; base += 32) {
        int rem = o1 - base;
        int m = rem < 32 ? rem : 32;
        int sj = 0;
        if (lane < m) sj = g_src_sorted[base + lane];
        for (int j = 0; j < m; j++) {
            int s = __shfl_sync(0xffffffffu, sj, j);
            float l2 = g_asrc[s * HEADS + h] + adst_d;
            l2 = (l2 > 0.f) ? l2 : 0.2f * l2;
            float aw = __expf(l2);
            wsum += aw;
            float4 v = __ldg(&xp4[(size_t)s * 32 + lane]);
            acc.x = fmaf(aw, v.x, acc.x);
            acc.y = fmaf(aw, v.y, acc.y);
            acc.z = fmaf(aw, v.z, acc.z);
            acc.w = fmaf(aw, v.w, acc.w);
        }
    }

    float inv_s = 1.0f / (wsum + 1e-16f);
    float4 gb = ((const float4*)gat_b)[lane];
    float4 v;
    v.x = fmaxf(acc.x * inv_s + gb.x, 0.f);
    v.y = fmaxf(acc.y * inv_s + gb.y, 0.f);
    v.z = fmaxf(acc.z * inv_s + gb.z, 0.f);
    v.w = fmaxf(acc.w * inv_s + gb.w, 0.f);
    float s = v.x + v.y + v.z + v.w;
    #pragma unroll
    for (int o = 16; o; o >>= 1) s += __shfl_xor_sync(0xffffffffu, s, o);
    float mu = s * (1.0f / DIM);
    float dx = v.x - mu, dy = v.y - mu, dz = v.z - mu, dw = v.w - mu;
    float ss = dx * dx + dy * dy + dz * dz + dw * dw;
    #pragma unroll
    for (int o = 16; o; o >>= 1) ss += __shfl_xor_sync(0xffffffffu, ss, o);
    float inv = rsqrtf(ss * (1.0f / DIM) + 1e-5f);
    float4 g = ((const float4*)ln2g)[lane];
    float4 b = ((const float4*)ln2b)[lane];
    float4 hres = ((const float4*)g_h)[(size_t)node * 32 + lane];
    float4 o4;
    o4.x = dx * inv * g.x + b.x + hres.x;
    o4.y = dy * inv * g.y + b.y + hres.y;
    o4.z = dz * inv * g.z + b.z + hres.z;
    o4.w = dw * inv * g.w + b.w + hres.w;
    ((float4*)outp)[(size_t)node * 32 + lane] = o4;
}

// ---------------- launch ----------------
extern "C" void kernel_launch(void* const* d_in, const int* in_sizes, int n_in,
                              void* d_out, int out_size) {
    const float* x      = (const float*)d_in[0];
    const int*   ei     = (const int*)d_in[1];
    const float* ea     = (const float*)d_in[2];
    const float* eps    = (const float*)d_in[3];
    const float* w1     = (const float*)d_in[4];
    const float* b1     = (const float*)d_in[5];
    const float* w2     = (const float*)d_in[6];
    const float* b2     = (const float*)d_in[7];
    const float* ln1_g  = (const float*)d_in[8];
    const float* ln1_b  = (const float*)d_in[9];
    const float* gat_w  = (const float*)d_in[10];
    const float* att_s  = (const float*)d_in[11];
    const float* att_d  = (const float*)d_in[12];
    const float* gat_b  = (const float*)d_in[13];
    const float* ln2_g  = (const float*)d_in[14];
    const float* ln2_b  = (const float*)d_in[15];
    float* outp = (float*)d_out;

    cudaFuncSetAttribute(k_fused_gemm, cudaFuncAttributeMaxDynamicSharedMemorySize, SMEM_BYTES);

    const int scan_blocks = (NN + 1023) / 1024;   // 98
    const int edge_blocks = EE / 256;             // 6250
    const int node_blocks = (NN * 32) / 256;      // 12500
    const int gemm_blocks = (NN + 63) / 64;       // 1563

    // CSR build (by dst)
    k_zero_deg<<<scan_blocks, 1024>>>();
    k_hist<<<edge_blocks, 256>>>(ei);
    k_scan1<<<scan_blocks, 1024>>>();
    k_scan2<<<1, 128>>>(scan_blocks);
    k_scan3<<<scan_blocks, 1024>>>();
    k_scatter<<<edge_blocks, 256>>>(ei);

    // GINE aggregation (gather, fused (1+eps)*x)
    k_gine_gather<<<node_blocks, 256>>>(x, ea, eps);

    // MLP + LN1 + residual + gat projection + attention coefficients (tf32x2 MMA)
    k_fused_gemm<<<gemm_blocks, 256, SMEM_BYTES>>>(x, w1, b1, w2, b2,
                                                   ln1_g, ln1_b, gat_w, att_s, att_d);

    // GAT aggregation (gather, fused softmax + bias + relu + LN2 + residual)
    k_gat_gather<<<node_blocks, 256>>>(gat_b, ln2_g, ln2_b, outp);
}